// round 9
// baseline (speedup 1.0000x reference)
#include <cuda_runtime.h>
#include <cuda_bf16.h>
#include <cstdint>

#define BATCH 64
#define CIN   384
#define COUT  384
#define NEXP  8
#define HW    784
#define KC     32
#define NCHUNK 12          // CIN / KC
#define CLUSTER_N 7        // n-tiles per batch = cluster size

#if defined(__CUDA_ARCH__) && (defined(__CUDA_ARCH_FEAT_SM103_ALL) || \
    defined(__CUDA_ARCH_FEAT_SM100_ALL) || defined(__CUDA_ARCH_SPECIFIC__) || \
    defined(__CUDA_ARCH_FAMILY_SPECIFIC__))
#define HAS_TCGEN05 1
#else
#define HAS_TCGEN05 0
#endif

// ---------------- device scratch (A terms only; x is consumed raw) ----------
__device__ __align__(1024) __nv_bfloat16 g_a_hi[BATCH * NCHUNK * COUT * KC];
__device__ __align__(1024) __nv_bfloat16 g_a_lo[BATCH * NCHUNK * COUT * KC];

__device__ __forceinline__ uint32_t sw64(uint32_t off) {
    return off ^ ((off >> 3) & 0x30);
}

// ---------------------------------------------------------------------------
// Kernel 1: agg[b,o,i] = sum_e rw[b,e]*w[e,o,i] -> chunk-major SW64 bf16 hi/lo
// ---------------------------------------------------------------------------
__global__ __launch_bounds__(256)
void agg_kernel(const float* __restrict__ rw, const float* __restrict__ w,
                __nv_bfloat16* __restrict__ ah, __nv_bfloat16* __restrict__ al)
{
    __shared__ float s_rw[BATCH * NEXP];
    const int tid = threadIdx.x;
    for (int i = tid; i < BATCH * NEXP; i += blockDim.x) s_rw[i] = rw[i];
    __syncthreads();

    const int oi = blockIdx.x * blockDim.x + tid;
    if (oi >= COUT * CIN) return;
    const int o = oi / CIN, i = oi % CIN;
    const int chunk = i >> 5;
    const uint32_t sw = sw64((uint32_t)(o * 64 + (i & 31) * 2));
    const size_t coff = ((size_t)chunk) * (COUT * 64) + sw;

    float we[NEXP];
#pragma unroll
    for (int e = 0; e < NEXP; e++) we[e] = w[e * (COUT * CIN) + oi];

    char* ahb = (char*)ah;
    char* alb = (char*)al;
#pragma unroll 4
    for (int b = 0; b < BATCH; b++) {
        float acc = 0.f;
#pragma unroll
        for (int e = 0; e < NEXP; e++) acc = fmaf(s_rw[b * NEXP + e], we[e], acc);
        __nv_bfloat16 h = __float2bfloat16(acc);
        __nv_bfloat16 l = __float2bfloat16(acc - __bfloat162float(h));
        size_t base = ((size_t)b * NCHUNK) * (COUT * 64) + coff;
        *reinterpret_cast<__nv_bfloat16*>(ahb + base) = h;
        *reinterpret_cast<__nv_bfloat16*>(alb + base) = l;
    }
}

// ---------------------------------------------------------------------------
// Kernel 2: fused convert+GEMM, warp-specialized + 7-CTA cluster multicast A.
// Roles: warps 0-3 convert x (+epilogue), warp 4 lane0 = x producer,
//        warp 5 lane0 = MMA issuer, warp 6 lane0 (rank 0 only) = A multicaster.
// ---------------------------------------------------------------------------
#define TN 112                      // 784 = 7*112
#define NTHREADS 224

#define AT_BYTES (COUT * 64)        // 24576 per A term per chunk
#define XC_BYTES (TN * 64)          // 7168 per converted X term
#define XR_BYTES (KC * TN * 4)      // 14336 raw fp32 x tile
#define AH_OFF 0
#define AL_OFF AT_BYTES
#define XH_OFF (2 * AT_BYTES)
#define XL_OFF (2 * AT_BYTES + XC_BYTES)
#define XR_OFF (2 * AT_BYTES + 2 * XC_BYTES)
#define STAGE_BYTES (XR_OFF + XR_BYTES)            // 77824
#define TOT_TX (2 * AT_BYTES + XR_BYTES)           // 63488
#define NSTAGE 2
#define SM_STAGE0 1024
#define SM_TOTAL (SM_STAGE0 + NSTAGE * STAGE_BYTES)  // 156672

// idesc: F32 accum, BF16 x BF16, K-major both, N=112, M=128
#define IDESC ((1u << 4) | (1u << 7) | (1u << 10) | ((TN / 8) << 17) | ((128 / 16) << 24))

#if HAS_TCGEN05
__device__ __forceinline__ uint32_t smem_u32(const void* p) {
    uint32_t a;
    asm("{ .reg .u64 t; cvta.to.shared.u64 t, %1; cvt.u32.u64 %0, t; }" : "=r"(a) : "l"(p));
    return a;
}
__device__ __forceinline__ uint32_t ctarank() {
    uint32_t r;
    asm("mov.u32 %0, %%cluster_ctarank;" : "=r"(r));
    return r;
}

#define MBARRIER_INIT(addr, cnt) \
    asm volatile("mbarrier.init.shared.b64 [%0], %1;" :: "r"(addr), "r"(cnt) : "memory")
#define MBARRIER_EXPECT_TX(addr, tx) \
    asm volatile("mbarrier.arrive.expect_tx.shared.b64 _, [%0], %1;" \
        :: "r"(addr), "r"((uint32_t)(tx)) : "memory")
#define MBARRIER_ARRIVE(addr) \
    asm volatile("mbarrier.arrive.shared.b64 _, [%0];" :: "r"(addr) : "memory")
// Arrive on rank-0's barrier at same SMEM offset (cluster scope)
#define MBARRIER_ARRIVE_RANK0(local_addr) \
    asm volatile("{\n\t.reg .b32 ra;\n\t" \
        "mapa.shared::cluster.u32 ra, %0, 0;\n\t" \
        "mbarrier.arrive.shared::cluster.b64 _, [ra];\n\t}" \
        :: "r"((uint32_t)(local_addr)) : "memory")

#define MBARRIER_WAIT_PARITY(addr, par) do {                                   \
    uint32_t _m = (addr), _p = (par), _d;                                      \
    asm volatile("{\n\t.reg .pred p;\n\t"                                      \
        "mbarrier.try_wait.parity.acquire.cta.shared::cta.b64 p, [%1], %2;\n\t"\
        "selp.b32 %0, 1, 0, p;\n\t}" : "=r"(_d) : "r"(_m), "r"(_p) : "memory");\
    if (!_d) {                                                                 \
        asm volatile("{\n\t.reg .pred P1;\n\t"                                 \
            "WL_%=:\n\t"                                                       \
            "mbarrier.try_wait.parity.acquire.cta.shared::cta.b64 P1, [%0], %1, 0x989680;\n\t" \
            "@P1 bra.uni WD_%=;\n\t"                                           \
            "bra.uni WL_%=;\n\t"                                               \
            "WD_%=:\n\t}" :: "r"(_m), "r"(_p) : "memory");                     \
    }                                                                          \
} while (0)

#define BULK_G2S(dst, src, bytes, mbar) \
    asm volatile("cp.async.bulk.shared::cluster.global.mbarrier::complete_tx::bytes " \
        "[%0], [%1], %2, [%3];" \
        :: "r"(dst), "l"(src), "r"((uint32_t)(bytes)), "r"(mbar) : "memory")
#define BULK_G2S_MC(dst, src, bytes, mbar, mask) \
    asm volatile("cp.async.bulk.shared::cluster.global.mbarrier::complete_tx::bytes.multicast::cluster " \
        "[%0], [%1], %2, [%3], %4;" \
        :: "r"(dst), "l"(src), "r"((uint32_t)(bytes)), "r"(mbar), "h"((uint16_t)(mask)) : "memory")

#define CLUSTER_SYNC() do { \
    asm volatile("barrier.cluster.arrive.aligned;" ::: "memory"); \
    asm volatile("barrier.cluster.wait.aligned;" ::: "memory"); \
} while (0)

#define TCGEN05_ALLOC(sm_res, n) \
    asm volatile("tcgen05.alloc.cta_group::1.sync.aligned.shared::cta.b32 [%0], %1;" \
        :: "r"(sm_res), "r"((uint32_t)(n)) : "memory")
#define TCGEN05_RELINQ() \
    asm volatile("tcgen05.relinquish_alloc_permit.cta_group::1.sync.aligned;")
#define TCGEN05_DEALLOC(t, n) \
    asm volatile("tcgen05.dealloc.cta_group::1.sync.aligned.b32 %0, %1;" :: "r"(t), "r"((uint32_t)(n)))
#define TCGEN05_COMMIT(mbar) \
    asm volatile("tcgen05.commit.cta_group::1.mbarrier::arrive::one.shared::cluster.b64 [%0];" \
        :: "r"(mbar) : "memory")
#define TCGEN05_FENCE_AFTER()  asm volatile("tcgen05.fence::after_thread_sync;" ::: "memory")
#define TCGEN05_FENCE_BEFORE() asm volatile("tcgen05.fence::before_thread_sync;" ::: "memory")
#define TCGEN05_WAIT_LD()      asm volatile("tcgen05.wait::ld.sync.aligned;" ::: "memory")
#define FENCE_ASYNC_SHARED()   asm volatile("fence.proxy.async.shared::cta;" ::: "memory")

__device__ __forceinline__ void mma_f16_ss(uint32_t d, uint64_t a, uint64_t b,
                                           uint32_t idesc, uint32_t en) {
    asm volatile("{\n\t.reg .pred p;\n\t"
        "setp.ne.u32 p, %5, 0;\n\t"
        "tcgen05.mma.cta_group::1.kind::f16 [%0], %1, %2, %3, {%4, %4, %4, %4}, p;\n\t}"
        :: "r"(d), "l"(a), "l"(b), "r"(idesc), "r"(0u), "r"(en) : "memory");
}

// SW64 K-major descriptor: layout=4, version=1, SBO=32, LBO=1
static constexpr uint64_t DESC_BASE_SW64 =
    (uint64_t(4) << 61) | (uint64_t(1) << 46) | (uint64_t(32) << 32) | (uint64_t(1) << 16);
#define MAKE_DESC(a) (DESC_BASE_SW64 | ((uint64_t)((a) >> 4) & 0x3FFF))

#define LDTM_X32(r, t) \
    asm volatile("tcgen05.ld.sync.aligned.32x32b.x32.b32 " \
        "{%0,%1,%2,%3,%4,%5,%6,%7,%8,%9,%10,%11,%12,%13,%14,%15," \
        "%16,%17,%18,%19,%20,%21,%22,%23,%24,%25,%26,%27,%28,%29,%30,%31}, [%32];" \
        : "=r"((r)[0]),"=r"((r)[1]),"=r"((r)[2]),"=r"((r)[3]),"=r"((r)[4]),"=r"((r)[5]),"=r"((r)[6]),"=r"((r)[7]), \
          "=r"((r)[8]),"=r"((r)[9]),"=r"((r)[10]),"=r"((r)[11]),"=r"((r)[12]),"=r"((r)[13]),"=r"((r)[14]),"=r"((r)[15]), \
          "=r"((r)[16]),"=r"((r)[17]),"=r"((r)[18]),"=r"((r)[19]),"=r"((r)[20]),"=r"((r)[21]),"=r"((r)[22]),"=r"((r)[23]), \
          "=r"((r)[24]),"=r"((r)[25]),"=r"((r)[26]),"=r"((r)[27]),"=r"((r)[28]),"=r"((r)[29]),"=r"((r)[30]),"=r"((r)[31]) \
        : "r"(t))

#define LDTM_X16(r, t) \
    asm volatile("tcgen05.ld.sync.aligned.32x32b.x16.b32 " \
        "{%0,%1,%2,%3,%4,%5,%6,%7,%8,%9,%10,%11,%12,%13,%14,%15}, [%16];" \
        : "=r"((r)[0]),"=r"((r)[1]),"=r"((r)[2]),"=r"((r)[3]),"=r"((r)[4]),"=r"((r)[5]),"=r"((r)[6]),"=r"((r)[7]), \
          "=r"((r)[8]),"=r"((r)[9]),"=r"((r)[10]),"=r"((r)[11]),"=r"((r)[12]),"=r"((r)[13]),"=r"((r)[14]),"=r"((r)[15]) \
        : "r"(t))
#endif  // HAS_TCGEN05

__global__ __launch_bounds__(NTHREADS, 1) __cluster_dims__(CLUSTER_N, 1, 1)
void gemm_kernel(const __nv_bfloat16* __restrict__ ah,
                 const __nv_bfloat16* __restrict__ al,
                 const float* __restrict__ x,
                 const float* __restrict__ rw,
                 const float* __restrict__ w,
                 float* __restrict__ out)
{
    extern __shared__ char smem[];
    const int tid = threadIdx.x;
    const int n0 = blockIdx.x * TN;
    const int b  = blockIdx.y;

#if HAS_TCGEN05
    (void)rw; (void)w;
    const uint32_t smem_base = smem_u32(smem);
    uint32_t full[NSTAGE], cbar[NSTAGE], mmad[NSTAGE], aempty[NSTAGE];
#pragma unroll
    for (int s = 0; s < NSTAGE; s++) {
        full[s]   = smem_base + 8  + 8 * s;
        cbar[s]   = smem_base + 24 + 8 * s;
        mmad[s]   = smem_base + 40 + 8 * s;
        aempty[s] = smem_base + 56 + 8 * s;
    }
    const uint32_t mb_done = smem_base + 72;

    const int wid = tid >> 5, lid = tid & 31;
    const uint32_t rank = ctarank();

    if (wid == 0) TCGEN05_ALLOC(smem_base, 512);
    if (tid == 0) {
#pragma unroll
        for (int s = 0; s < NSTAGE; s++) {
            MBARRIER_INIT(full[s], 1);
            MBARRIER_INIT(cbar[s], 128);       // converter warps 0-3
            MBARRIER_INIT(mmad[s], 1);
            MBARRIER_INIT(aempty[s], CLUSTER_N);
        }
        MBARRIER_INIT(mb_done, 1);
        // Arm stages 0,1 BEFORE any multicast can land (pre-cluster-sync)
        MBARRIER_EXPECT_TX(full[0], TOT_TX);
        MBARRIER_EXPECT_TX(full[1], TOT_TX);
    }
    if (wid == 0) TCGEN05_RELINQ();
    __syncthreads();
    CLUSTER_SYNC();   // all CTAs' barriers initialized + armed

    uint32_t tmem_base;
    asm volatile("ld.shared.b32 %0, [%1];" : "=r"(tmem_base) : "r"(smem_base));

    // GMEM bases
    const char*  gah = (const char*)ah + (size_t)b * NCHUNK * AT_BYTES;
    const char*  gal = (const char*)al + (size_t)b * NCHUNK * AT_BYTES;
    const float* gx  = x + (size_t)b * CIN * HW + n0;   // rows stride HW

    if (wid == 4) {
        // ---------------- x producer (lane 0, every CTA) ----------------
        if (lid == 0) {
            for (int c = 0; c < NCHUNK; c++) {
                const int s = c & 1;
                if (c >= 2) {
                    MBARRIER_WAIT_PARITY(mmad[s], ((c - 2) >> 1) & 1);
                    MBARRIER_EXPECT_TX(full[s], TOT_TX);   // arm before releasing A
                    MBARRIER_ARRIVE_RANK0(aempty[s]);      // "my stage s is empty"
                }
                const uint32_t stg = smem_base + SM_STAGE0 + s * STAGE_BYTES;
#pragma unroll
                for (int kk = 0; kk < KC; kk++)
                    BULK_G2S(stg + XR_OFF + kk * (TN * 4),
                             gx + (size_t)(c * KC + kk) * HW, TN * 4, full[s]);
            }
        }
    } else if (wid == 5) {
        // ---------------- MMA issuer (lane 0, every CTA) ----------------
        if (lid == 0) {
            for (int c = 0; c < NCHUNK; c++) {
                const int s = c & 1;
                MBARRIER_WAIT_PARITY(cbar[s], (c >> 1) & 1);
                const uint32_t stg = smem_base + SM_STAGE0 + s * STAGE_BYTES;
                const uint64_t dah = MAKE_DESC(stg + AH_OFF);
                const uint64_t dal = MAKE_DESC(stg + AL_OFF);
                const uint64_t dxh = MAKE_DESC(stg + XH_OFF);
                const uint64_t dxl = MAKE_DESC(stg + XL_OFF);
#pragma unroll
                for (int t = 0; t < 3; t++) {
                    const uint32_t d  = tmem_base + t * TN;
                    const uint64_t at = (uint64_t)t * 512;   // 128 rows * 64B / 16
                    mma_f16_ss(d, dah + at,     dxh,     IDESC, c > 0 ? 1u : 0u);
                    mma_f16_ss(d, dah + at + 2, dxh + 2, IDESC, 1u);
                    mma_f16_ss(d, dal + at,     dxh,     IDESC, 1u);
                    mma_f16_ss(d, dal + at + 2, dxh + 2, IDESC, 1u);
                    mma_f16_ss(d, dah + at,     dxl,     IDESC, 1u);
                    mma_f16_ss(d, dah + at + 2, dxl + 2, IDESC, 1u);
                }
                TCGEN05_COMMIT(c == NCHUNK - 1 ? mb_done : mmad[s]);
            }
        }
    } else if (wid == 6) {
        // ---------------- A multicaster (rank 0 only, lane 0) ----------------
        if (rank == 0 && lid == 0) {
            for (int c = 0; c < NCHUNK; c++) {
                const int s = c & 1;
                if (c >= 2) MBARRIER_WAIT_PARITY(aempty[s], ((c - 2) >> 1) & 1);
                const uint32_t stg = smem_base + SM_STAGE0 + s * STAGE_BYTES;
                BULK_G2S_MC(stg + AH_OFF, gah + (size_t)c * AT_BYTES, AT_BYTES,
                            full[s], 0x7F);
                BULK_G2S_MC(stg + AL_OFF, gal + (size_t)c * AT_BYTES, AT_BYTES,
                            full[s], 0x7F);
            }
        }
    } else {
        // ---------------- converters (warps 0-3) ----------------
        const int ncv = tid;          // 0..127; rows 0..111 valid
        for (int c = 0; c < NCHUNK; c++) {
            const int s = c & 1;
            MBARRIER_WAIT_PARITY(full[s], (c >> 1) & 1);
            char* stp = smem + SM_STAGE0 + s * STAGE_BYTES;
            if (ncv < TN) {
                const float* xr = reinterpret_cast<const float*>(stp + XR_OFF);
                uint32_t hw_[16], lw_[16];
#pragma unroll
                for (int kk = 0; kk < 16; kk++) {
                    float v0 = xr[(2 * kk) * TN + ncv];
                    float v1 = xr[(2 * kk + 1) * TN + ncv];
                    __nv_bfloat16 h0 = __float2bfloat16(v0);
                    __nv_bfloat16 h1 = __float2bfloat16(v1);
                    __nv_bfloat16 l0 = __float2bfloat16(v0 - __bfloat162float(h0));
                    __nv_bfloat16 l1 = __float2bfloat16(v1 - __bfloat162float(h1));
                    __nv_bfloat162 hp = {h0, h1}, lp = {l0, l1};
                    hw_[kk] = *reinterpret_cast<uint32_t*>(&hp);
                    lw_[kk] = *reinterpret_cast<uint32_t*>(&lp);
                }
#pragma unroll
                for (int q = 0; q < 4; q++) {
                    uint32_t off = sw64((uint32_t)(ncv * 64 + q * 16));
                    *reinterpret_cast<uint4*>(stp + XH_OFF + off) =
                        make_uint4(hw_[4*q], hw_[4*q+1], hw_[4*q+2], hw_[4*q+3]);
                    *reinterpret_cast<uint4*>(stp + XL_OFF + off) =
                        make_uint4(lw_[4*q], lw_[4*q+1], lw_[4*q+2], lw_[4*q+3]);
                }
            }
            FENCE_ASYNC_SHARED();
            MBARRIER_ARRIVE(cbar[s]);
        }
    }

    // ---- epilogue ----
    MBARRIER_WAIT_PARITY(mb_done, 0);
    TCGEN05_FENCE_AFTER();

    if (wid < 4) {
        uint32_t r[32];
#pragma unroll
        for (int t = 0; t < 3; t++) {
            const int m = t * 128 + wid * 32 + lid;
            float* orow = out + ((size_t)b * COUT + m) * HW + n0;
            const uint32_t tb = tmem_base + t * TN;

            LDTM_X32(r, tb);
            TCGEN05_WAIT_LD();
#pragma unroll
            for (int q = 0; q < 8; q++)
                *reinterpret_cast<float4*>(orow + q * 4) =
                    make_float4(__uint_as_float(r[q*4]), __uint_as_float(r[q*4+1]),
                                __uint_as_float(r[q*4+2]), __uint_as_float(r[q*4+3]));
            LDTM_X32(r, tb + 32);
            TCGEN05_WAIT_LD();
#pragma unroll
            for (int q = 0; q < 8; q++)
                *reinterpret_cast<float4*>(orow + 32 + q * 4) =
                    make_float4(__uint_as_float(r[q*4]), __uint_as_float(r[q*4+1]),
                                __uint_as_float(r[q*4+2]), __uint_as_float(r[q*4+3]));
            LDTM_X32(r, tb + 64);
            TCGEN05_WAIT_LD();
#pragma unroll
            for (int q = 0; q < 8; q++)
                *reinterpret_cast<float4*>(orow + 64 + q * 4) =
                    make_float4(__uint_as_float(r[q*4]), __uint_as_float(r[q*4+1]),
                                __uint_as_float(r[q*4+2]), __uint_as_float(r[q*4+3]));
            LDTM_X16(r, tb + 96);
            TCGEN05_WAIT_LD();
#pragma unroll
            for (int q = 0; q < 4; q++)
                *reinterpret_cast<float4*>(orow + 96 + q * 4) =
                    make_float4(__uint_as_float(r[q*4]), __uint_as_float(r[q*4+1]),
                                __uint_as_float(r[q*4+2]), __uint_as_float(r[q*4+3]));
        }
        TCGEN05_FENCE_BEFORE();
    }

    __syncthreads();
    if (wid == 0) TCGEN05_DEALLOC(tmem_base, 512);
    CLUSTER_SYNC();   // no CTA exits while peer multicasts may be in flight

#else  // ---------- SIMT fallback (compute_103 pass only; never executes) ----
    (void)ah; (void)al; (void)smem;
    for (int idx = tid; idx < COUT * TN; idx += NTHREADS) {
        const int o = idx / TN;
        const int n = n0 + idx % TN;
        float acc = 0.f;
        for (int k = 0; k < CIN; k++) {
            float a = 0.f;
#pragma unroll
            for (int e = 0; e < NEXP; e++)
                a = fmaf(rw[b * NEXP + e], w[(size_t)e * COUT * CIN + o * CIN + k], a);
            acc = fmaf(a, x[(size_t)b * CIN * HW + (size_t)k * HW + n], acc);
        }
        out[((size_t)b * COUT + o) * HW + n] = acc;
    }
#endif
}

// ---------------------------------------------------------------------------
extern "C" void kernel_launch(void* const* d_in, const int* in_sizes, int n_in,
                              void* d_out, int out_size)
{
    const float* x  = (const float*)d_in[0];
    const float* rw = (const float*)d_in[1];
    const float* w  = (const float*)d_in[2];
    float* out = (float*)d_out;

    __nv_bfloat16 *ah, *al;
    cudaGetSymbolAddress((void**)&ah, g_a_hi);
    cudaGetSymbolAddress((void**)&al, g_a_lo);

    {
        const int total = COUT * CIN;
        agg_kernel<<<(total + 255) / 256, 256>>>(rw, w, ah, al);
    }
    {
        cudaFuncSetAttribute(gemm_kernel, cudaFuncAttributeMaxDynamicSharedMemorySize, SM_TOTAL);
        dim3 grid(HW / TN, BATCH);   // 7 x 64 = 448 CTAs, clusters of 7 (one batch)
        gemm_kernel<<<grid, NTHREADS, SM_TOTAL>>>(ah, al, x, rw, w, out);
    }
}

// round 10
// speedup vs baseline: 1.4932x; 1.4932x over previous
#include <cuda_runtime.h>
#include <cuda_bf16.h>
#include <cstdint>

#define BATCH 64
#define CIN   384
#define COUT  384
#define NEXP  8
#define HW    784
#define KC     32
#define NCHUNK 12          // CIN / KC

#if defined(__CUDA_ARCH__) && (defined(__CUDA_ARCH_FEAT_SM103_ALL) || \
    defined(__CUDA_ARCH_FEAT_SM100_ALL) || defined(__CUDA_ARCH_SPECIFIC__) || \
    defined(__CUDA_ARCH_FAMILY_SPECIFIC__))
#define HAS_TCGEN05 1
#else
#define HAS_TCGEN05 0
#endif

// ---------------- device scratch (A terms only; x is consumed raw) ----------
__device__ __align__(1024) __nv_bfloat16 g_a_hi[BATCH * NCHUNK * COUT * KC];
__device__ __align__(1024) __nv_bfloat16 g_a_lo[BATCH * NCHUNK * COUT * KC];

__device__ __forceinline__ uint32_t sw64(uint32_t off) {
    return off ^ ((off >> 3) & 0x30);
}

// ---------------------------------------------------------------------------
// Kernel 1: agg[b,o,i] = sum_e rw[b,e]*w[e,o,i] -> chunk-major SW64 bf16 hi/lo
// ---------------------------------------------------------------------------
__global__ __launch_bounds__(256)
void agg_kernel(const float* __restrict__ rw, const float* __restrict__ w,
                __nv_bfloat16* __restrict__ ah, __nv_bfloat16* __restrict__ al)
{
    __shared__ float s_rw[BATCH * NEXP];
    const int tid = threadIdx.x;
    for (int i = tid; i < BATCH * NEXP; i += blockDim.x) s_rw[i] = rw[i];
    __syncthreads();

    const int oi = blockIdx.x * blockDim.x + tid;
    if (oi >= COUT * CIN) return;
    const int o = oi / CIN, i = oi % CIN;
    const int chunk = i >> 5;
    const uint32_t sw = sw64((uint32_t)(o * 64 + (i & 31) * 2));
    const size_t coff = ((size_t)chunk) * (COUT * 64) + sw;

    float we[NEXP];
#pragma unroll
    for (int e = 0; e < NEXP; e++) we[e] = w[e * (COUT * CIN) + oi];

    char* ahb = (char*)ah;
    char* alb = (char*)al;
#pragma unroll 4
    for (int b = 0; b < BATCH; b++) {
        float acc = 0.f;
#pragma unroll
        for (int e = 0; e < NEXP; e++) acc = fmaf(s_rw[b * NEXP + e], we[e], acc);
        __nv_bfloat16 h = __float2bfloat16(acc);
        __nv_bfloat16 l = __float2bfloat16(acc - __bfloat162float(h));
        size_t base = ((size_t)b * NCHUNK) * (COUT * 64) + coff;
        *reinterpret_cast<__nv_bfloat16*>(ahb + base) = h;
        *reinterpret_cast<__nv_bfloat16*>(alb + base) = l;
    }
}

// ---------------------------------------------------------------------------
// Kernel 2: fused convert+GEMM, warp-specialized.
// Per CTA: C[384,112] for one (b, n-tile).
// Roles: warps 0-3 convert x (+epilogue), warp 4 = bulk-load producer
//        (TMA issue spread across all 32 lanes), warp 5 lane0 = MMA issuer.
// ---------------------------------------------------------------------------
#define TN 112                      // 784 = 7*112
#define NTHREADS 192

#define AT_BYTES (COUT * 64)        // 24576 per A term per chunk
#define XC_BYTES (TN * 64)          // 7168 per converted X term
#define XR_BYTES (KC * TN * 4)      // 14336 raw fp32 x tile
#define AH_OFF 0
#define AL_OFF AT_BYTES
#define XH_OFF (2 * AT_BYTES)
#define XL_OFF (2 * AT_BYTES + XC_BYTES)
#define XR_OFF (2 * AT_BYTES + 2 * XC_BYTES)
#define STAGE_BYTES (XR_OFF + XR_BYTES)            // 77824
#define TOT_TX (2 * AT_BYTES + XR_BYTES)           // 63488
#define NSTAGE 2
#define SM_STAGE0 1024
#define SM_TOTAL (SM_STAGE0 + NSTAGE * STAGE_BYTES)  // 156672

// idesc: F32 accum, BF16 x BF16, K-major both, N=112, M=128
#define IDESC ((1u << 4) | (1u << 7) | (1u << 10) | ((TN / 8) << 17) | ((128 / 16) << 24))

#if HAS_TCGEN05
__device__ __forceinline__ uint32_t smem_u32(const void* p) {
    uint32_t a;
    asm("{ .reg .u64 t; cvta.to.shared.u64 t, %1; cvt.u32.u64 %0, t; }" : "=r"(a) : "l"(p));
    return a;
}

#define MBARRIER_INIT(addr, cnt) \
    asm volatile("mbarrier.init.shared.b64 [%0], %1;" :: "r"(addr), "r"(cnt) : "memory")
#define MBARRIER_EXPECT_TX(addr, tx) \
    asm volatile("mbarrier.arrive.expect_tx.shared.b64 _, [%0], %1;" \
        :: "r"(addr), "r"((uint32_t)(tx)) : "memory")
#define MBARRIER_ARRIVE(addr) \
    asm volatile("mbarrier.arrive.shared.b64 _, [%0];" :: "r"(addr) : "memory")

#define MBARRIER_WAIT_PARITY(addr, par) do {                                   \
    uint32_t _m = (addr), _p = (par), _d;                                      \
    asm volatile("{\n\t.reg .pred p;\n\t"                                      \
        "mbarrier.try_wait.parity.acquire.cta.shared::cta.b64 p, [%1], %2;\n\t"\
        "selp.b32 %0, 1, 0, p;\n\t}" : "=r"(_d) : "r"(_m), "r"(_p) : "memory");\
    if (!_d) {                                                                 \
        asm volatile("{\n\t.reg .pred P1;\n\t"                                 \
            "WL_%=:\n\t"                                                       \
            "mbarrier.try_wait.parity.acquire.cta.shared::cta.b64 P1, [%0], %1, 0x989680;\n\t" \
            "@P1 bra.uni WD_%=;\n\t"                                           \
            "bra.uni WL_%=;\n\t"                                               \
            "WD_%=:\n\t}" :: "r"(_m), "r"(_p) : "memory");                     \
    }                                                                          \
} while (0)

#define BULK_G2S(dst, src, bytes, mbar) \
    asm volatile("cp.async.bulk.shared::cluster.global.mbarrier::complete_tx::bytes " \
        "[%0], [%1], %2, [%3];" \
        :: "r"(dst), "l"(src), "r"((uint32_t)(bytes)), "r"(mbar) : "memory")

#define TCGEN05_ALLOC(sm_res, n) \
    asm volatile("tcgen05.alloc.cta_group::1.sync.aligned.shared::cta.b32 [%0], %1;" \
        :: "r"(sm_res), "r"((uint32_t)(n)) : "memory")
#define TCGEN05_RELINQ() \
    asm volatile("tcgen05.relinquish_alloc_permit.cta_group::1.sync.aligned;")
#define TCGEN05_DEALLOC(t, n) \
    asm volatile("tcgen05.dealloc.cta_group::1.sync.aligned.b32 %0, %1;" :: "r"(t), "r"((uint32_t)(n)))
#define TCGEN05_COMMIT(mbar) \
    asm volatile("tcgen05.commit.cta_group::1.mbarrier::arrive::one.shared::cluster.b64 [%0];" \
        :: "r"(mbar) : "memory")
#define TCGEN05_FENCE_AFTER()  asm volatile("tcgen05.fence::after_thread_sync;" ::: "memory")
#define TCGEN05_FENCE_BEFORE() asm volatile("tcgen05.fence::before_thread_sync;" ::: "memory")
#define TCGEN05_WAIT_LD()      asm volatile("tcgen05.wait::ld.sync.aligned;" ::: "memory")
#define FENCE_ASYNC_SHARED()   asm volatile("fence.proxy.async.shared::cta;" ::: "memory")

__device__ __forceinline__ void mma_f16_ss(uint32_t d, uint64_t a, uint64_t b,
                                           uint32_t idesc, uint32_t en) {
    asm volatile("{\n\t.reg .pred p;\n\t"
        "setp.ne.u32 p, %5, 0;\n\t"
        "tcgen05.mma.cta_group::1.kind::f16 [%0], %1, %2, %3, {%4, %4, %4, %4}, p;\n\t}"
        :: "r"(d), "l"(a), "l"(b), "r"(idesc), "r"(0u), "r"(en) : "memory");
}

// SW64 K-major descriptor: layout=4, version=1, SBO=32, LBO=1
static constexpr uint64_t DESC_BASE_SW64 =
    (uint64_t(4) << 61) | (uint64_t(1) << 46) | (uint64_t(32) << 32) | (uint64_t(1) << 16);
#define MAKE_DESC(a) (DESC_BASE_SW64 | ((uint64_t)((a) >> 4) & 0x3FFF))

#define LDTM_X32(r, t) \
    asm volatile("tcgen05.ld.sync.aligned.32x32b.x32.b32 " \
        "{%0,%1,%2,%3,%4,%5,%6,%7,%8,%9,%10,%11,%12,%13,%14,%15," \
        "%16,%17,%18,%19,%20,%21,%22,%23,%24,%25,%26,%27,%28,%29,%30,%31}, [%32];" \
        : "=r"((r)[0]),"=r"((r)[1]),"=r"((r)[2]),"=r"((r)[3]),"=r"((r)[4]),"=r"((r)[5]),"=r"((r)[6]),"=r"((r)[7]), \
          "=r"((r)[8]),"=r"((r)[9]),"=r"((r)[10]),"=r"((r)[11]),"=r"((r)[12]),"=r"((r)[13]),"=r"((r)[14]),"=r"((r)[15]), \
          "=r"((r)[16]),"=r"((r)[17]),"=r"((r)[18]),"=r"((r)[19]),"=r"((r)[20]),"=r"((r)[21]),"=r"((r)[22]),"=r"((r)[23]), \
          "=r"((r)[24]),"=r"((r)[25]),"=r"((r)[26]),"=r"((r)[27]),"=r"((r)[28]),"=r"((r)[29]),"=r"((r)[30]),"=r"((r)[31]) \
        : "r"(t))

#define LDTM_X16(r, t) \
    asm volatile("tcgen05.ld.sync.aligned.32x32b.x16.b32 " \
        "{%0,%1,%2,%3,%4,%5,%6,%7,%8,%9,%10,%11,%12,%13,%14,%15}, [%16];" \
        : "=r"((r)[0]),"=r"((r)[1]),"=r"((r)[2]),"=r"((r)[3]),"=r"((r)[4]),"=r"((r)[5]),"=r"((r)[6]),"=r"((r)[7]), \
          "=r"((r)[8]),"=r"((r)[9]),"=r"((r)[10]),"=r"((r)[11]),"=r"((r)[12]),"=r"((r)[13]),"=r"((r)[14]),"=r"((r)[15]) \
        : "r"(t))
#endif  // HAS_TCGEN05

__global__ __launch_bounds__(NTHREADS, 1)
void gemm_kernel(const __nv_bfloat16* __restrict__ ah,
                 const __nv_bfloat16* __restrict__ al,
                 const float* __restrict__ x,
                 const float* __restrict__ rw,
                 const float* __restrict__ w,
                 float* __restrict__ out)
{
    extern __shared__ char smem[];
    const int tid = threadIdx.x;
    const int n0 = blockIdx.x * TN;
    const int b  = blockIdx.y;

#if HAS_TCGEN05
    (void)rw; (void)w;
    const uint32_t smem_base = smem_u32(smem);
    uint32_t full[NSTAGE], cbar[NSTAGE], mmad[NSTAGE];
#pragma unroll
    for (int s = 0; s < NSTAGE; s++) {
        full[s] = smem_base + 8  + 8 * s;
        cbar[s] = smem_base + 24 + 8 * s;
        mmad[s] = smem_base + 40 + 8 * s;
    }
    const uint32_t mb_done = smem_base + 56;

    const int wid = tid >> 5, lid = tid & 31;

    if (wid == 0) TCGEN05_ALLOC(smem_base, 512);
    if (tid == 0) {
#pragma unroll
        for (int s = 0; s < NSTAGE; s++) {
            MBARRIER_INIT(full[s], 1);
            MBARRIER_INIT(cbar[s], 128);   // converter warps 0-3
            MBARRIER_INIT(mmad[s], 1);
        }
        MBARRIER_INIT(mb_done, 1);
    }
    if (wid == 0) TCGEN05_RELINQ();
    __syncthreads();

    uint32_t tmem_base;
    asm volatile("ld.shared.b32 %0, [%1];" : "=r"(tmem_base) : "r"(smem_base));

    // GMEM bases
    const char*  gah = (const char*)ah + (size_t)b * NCHUNK * AT_BYTES;
    const char*  gal = (const char*)al + (size_t)b * NCHUNK * AT_BYTES;
    const float* gx  = x + (size_t)b * CIN * HW + n0;   // rows stride HW

    if (wid == 4) {
        // ---------- producer warp: TMA issue spread across lanes ----------
        for (int c = 0; c < NCHUNK; c++) {
            const int s = c & 1;
            if (lid == 0) {
                if (c >= 2) MBARRIER_WAIT_PARITY(mmad[s], ((c - 2) >> 1) & 1);
                MBARRIER_EXPECT_TX(full[s], TOT_TX);
            }
            __syncwarp();
            const uint32_t stg = smem_base + SM_STAGE0 + s * STAGE_BYTES;
            // each lane issues one x row (mbarrier tx-count is signed: issue
            // order vs expect_tx order across lanes is safe)
            BULK_G2S(stg + XR_OFF + lid * (TN * 4),
                     gx + (size_t)(c * KC + lid) * HW, TN * 4, full[s]);
            if (lid == 0)
                BULK_G2S(stg + AH_OFF, gah + (size_t)c * AT_BYTES, AT_BYTES, full[s]);
            else if (lid == 1)
                BULK_G2S(stg + AL_OFF, gal + (size_t)c * AT_BYTES, AT_BYTES, full[s]);
        }
    } else if (wid == 5) {
        // ------------------- MMA issuer (lane 0) -------------------
        if (lid == 0) {
            for (int c = 0; c < NCHUNK; c++) {
                const int s = c & 1;
                MBARRIER_WAIT_PARITY(cbar[s], (c >> 1) & 1);
                const uint32_t stg = smem_base + SM_STAGE0 + s * STAGE_BYTES;
                const uint64_t dah = MAKE_DESC(stg + AH_OFF);
                const uint64_t dal = MAKE_DESC(stg + AL_OFF);
                const uint64_t dxh = MAKE_DESC(stg + XH_OFF);
                const uint64_t dxl = MAKE_DESC(stg + XL_OFF);
#pragma unroll
                for (int t = 0; t < 3; t++) {
                    const uint32_t d  = tmem_base + t * TN;
                    const uint64_t at = (uint64_t)t * 512;   // 128 rows * 64B / 16
                    mma_f16_ss(d, dah + at,     dxh,     IDESC, c > 0 ? 1u : 0u);
                    mma_f16_ss(d, dah + at + 2, dxh + 2, IDESC, 1u);
                    mma_f16_ss(d, dal + at,     dxh,     IDESC, 1u);
                    mma_f16_ss(d, dal + at + 2, dxh + 2, IDESC, 1u);
                    mma_f16_ss(d, dah + at,     dxl,     IDESC, 1u);
                    mma_f16_ss(d, dah + at + 2, dxl + 2, IDESC, 1u);
                }
                TCGEN05_COMMIT(c == NCHUNK - 1 ? mb_done : mmad[s]);
            }
        }
    } else {
        // ------------------- converters (warps 0-3) -------------------
        const int ncv = tid;          // 0..127; rows 0..111 valid
        for (int c = 0; c < NCHUNK; c++) {
            const int s = c & 1;
            MBARRIER_WAIT_PARITY(full[s], (c >> 1) & 1);
            char* stp = smem + SM_STAGE0 + s * STAGE_BYTES;
            if (ncv < TN) {
                const float* xr = reinterpret_cast<const float*>(stp + XR_OFF);
                uint32_t hw_[16], lw_[16];
#pragma unroll
                for (int kk = 0; kk < 16; kk++) {
                    float v0 = xr[(2 * kk) * TN + ncv];
                    float v1 = xr[(2 * kk + 1) * TN + ncv];
                    __nv_bfloat16 h0 = __float2bfloat16(v0);
                    __nv_bfloat16 h1 = __float2bfloat16(v1);
                    __nv_bfloat16 l0 = __float2bfloat16(v0 - __bfloat162float(h0));
                    __nv_bfloat16 l1 = __float2bfloat16(v1 - __bfloat162float(h1));
                    __nv_bfloat162 hp = {h0, h1}, lp = {l0, l1};
                    hw_[kk] = *reinterpret_cast<uint32_t*>(&hp);
                    lw_[kk] = *reinterpret_cast<uint32_t*>(&lp);
                }
#pragma unroll
                for (int q = 0; q < 4; q++) {
                    uint32_t off = sw64((uint32_t)(ncv * 64 + q * 16));
                    *reinterpret_cast<uint4*>(stp + XH_OFF + off) =
                        make_uint4(hw_[4*q], hw_[4*q+1], hw_[4*q+2], hw_[4*q+3]);
                    *reinterpret_cast<uint4*>(stp + XL_OFF + off) =
                        make_uint4(lw_[4*q], lw_[4*q+1], lw_[4*q+2], lw_[4*q+3]);
                }
            }
            FENCE_ASYNC_SHARED();
            MBARRIER_ARRIVE(cbar[s]);
        }
    }

    // ---- epilogue ----
    MBARRIER_WAIT_PARITY(mb_done, 0);
    TCGEN05_FENCE_AFTER();

    if (wid < 4) {
        uint32_t r[32];
#pragma unroll
        for (int t = 0; t < 3; t++) {
            const int m = t * 128 + wid * 32 + lid;
            float* orow = out + ((size_t)b * COUT + m) * HW + n0;
            const uint32_t tb = tmem_base + t * TN;

            LDTM_X32(r, tb);
            TCGEN05_WAIT_LD();
#pragma unroll
            for (int q = 0; q < 8; q++)
                *reinterpret_cast<float4*>(orow + q * 4) =
                    make_float4(__uint_as_float(r[q*4]), __uint_as_float(r[q*4+1]),
                                __uint_as_float(r[q*4+2]), __uint_as_float(r[q*4+3]));
            LDTM_X32(r, tb + 32);
            TCGEN05_WAIT_LD();
#pragma unroll
            for (int q = 0; q < 8; q++)
                *reinterpret_cast<float4*>(orow + 32 + q * 4) =
                    make_float4(__uint_as_float(r[q*4]), __uint_as_float(r[q*4+1]),
                                __uint_as_float(r[q*4+2]), __uint_as_float(r[q*4+3]));
            LDTM_X32(r, tb + 64);
            TCGEN05_WAIT_LD();
#pragma unroll
            for (int q = 0; q < 8; q++)
                *reinterpret_cast<float4*>(orow + 64 + q * 4) =
                    make_float4(__uint_as_float(r[q*4]), __uint_as_float(r[q*4+1]),
                                __uint_as_float(r[q*4+2]), __uint_as_float(r[q*4+3]));
            LDTM_X16(r, tb + 96);
            TCGEN05_WAIT_LD();
#pragma unroll
            for (int q = 0; q < 4; q++)
                *reinterpret_cast<float4*>(orow + 96 + q * 4) =
                    make_float4(__uint_as_float(r[q*4]), __uint_as_float(r[q*4+1]),
                                __uint_as_float(r[q*4+2]), __uint_as_float(r[q*4+3]));
        }
        TCGEN05_FENCE_BEFORE();
    }

    __syncthreads();
    if (wid == 0) TCGEN05_DEALLOC(tmem_base, 512);

#else  // ---------- SIMT fallback (compute_103 pass only; never executes) ----
    (void)ah; (void)al; (void)smem;
    for (int idx = tid; idx < COUT * TN; idx += NTHREADS) {
        const int o = idx / TN;
        const int n = n0 + idx % TN;
        float acc = 0.f;
        for (int k = 0; k < CIN; k++) {
            float a = 0.f;
#pragma unroll
            for (int e = 0; e < NEXP; e++)
                a = fmaf(rw[b * NEXP + e], w[(size_t)e * COUT * CIN + o * CIN + k], a);
            acc = fmaf(a, x[(size_t)b * CIN * HW + (size_t)k * HW + n], acc);
        }
        out[((size_t)b * COUT + o) * HW + n] = acc;
    }
#endif
}

// ---------------------------------------------------------------------------
extern "C" void kernel_launch(void* const* d_in, const int* in_sizes, int n_in,
                              void* d_out, int out_size)
{
    const float* x  = (const float*)d_in[0];
    const float* rw = (const float*)d_in[1];
    const float* w  = (const float*)d_in[2];
    float* out = (float*)d_out;

    __nv_bfloat16 *ah, *al;
    cudaGetSymbolAddress((void**)&ah, g_a_hi);
    cudaGetSymbolAddress((void**)&al, g_a_lo);

    {
        const int total = COUT * CIN;
        agg_kernel<<<(total + 255) / 256, 256>>>(rw, w, ah, al);
    }
    {
        cudaFuncSetAttribute(gemm_kernel, cudaFuncAttributeMaxDynamicSharedMemorySize, SM_TOTAL);
        dim3 grid(HW / TN, BATCH);   // 7 x 64 = 448 CTAs
        gemm_kernel<<<grid, NTHREADS, SM_TOTAL>>>(ah, al, x, rw, w, out);
    }
}

// round 11
// speedup vs baseline: 1.6346x; 1.0947x over previous
#include <cuda_runtime.h>
#include <cuda_bf16.h>
#include <cstdint>

#define BATCH 64
#define CIN   384
#define COUT  384
#define NEXP  8
#define HW    784
#define KC     32
#define NCHUNK 12          // CIN / KC

#if defined(__CUDA_ARCH__) && (defined(__CUDA_ARCH_FEAT_SM103_ALL) || \
    defined(__CUDA_ARCH_FEAT_SM100_ALL) || defined(__CUDA_ARCH_SPECIFIC__) || \
    defined(__CUDA_ARCH_FAMILY_SPECIFIC__))
#define HAS_TCGEN05 1
#else
#define HAS_TCGEN05 0
#endif

// ---------------- device scratch (A terms only; x is consumed raw) ----------
__device__ __align__(1024) __nv_bfloat16 g_a_hi[BATCH * NCHUNK * COUT * KC];
__device__ __align__(1024) __nv_bfloat16 g_a_lo[BATCH * NCHUNK * COUT * KC];

__device__ __forceinline__ uint32_t sw64(uint32_t off) {
    return off ^ ((off >> 3) & 0x30);
}

// ---------------------------------------------------------------------------
// Kernel 1: agg[b,o,i] = sum_e rw[b,e]*w[e,o,i] -> chunk-major SW64 bf16 hi/lo
// ---------------------------------------------------------------------------
__global__ __launch_bounds__(256)
void agg_kernel(const float* __restrict__ rw, const float* __restrict__ w,
                __nv_bfloat16* __restrict__ ah, __nv_bfloat16* __restrict__ al)
{
    __shared__ float s_rw[BATCH * NEXP];
    const int tid = threadIdx.x;
    for (int i = tid; i < BATCH * NEXP; i += blockDim.x) s_rw[i] = rw[i];
    __syncthreads();

    const int oi = blockIdx.x * blockDim.x + tid;
    if (oi >= COUT * CIN) return;
    const int o = oi / CIN, i = oi % CIN;
    const int chunk = i >> 5;
    const uint32_t sw = sw64((uint32_t)(o * 64 + (i & 31) * 2));
    const size_t coff = ((size_t)chunk) * (COUT * 64) + sw;

    float we[NEXP];
#pragma unroll
    for (int e = 0; e < NEXP; e++) we[e] = w[e * (COUT * CIN) + oi];

    char* ahb = (char*)ah;
    char* alb = (char*)al;
#pragma unroll 4
    for (int b = 0; b < BATCH; b++) {
        float acc = 0.f;
#pragma unroll
        for (int e = 0; e < NEXP; e++) acc = fmaf(s_rw[b * NEXP + e], we[e], acc);
        __nv_bfloat16 h = __float2bfloat16(acc);
        __nv_bfloat16 l = __float2bfloat16(acc - __bfloat162float(h));
        size_t base = ((size_t)b * NCHUNK) * (COUT * 64) + coff;
        *reinterpret_cast<__nv_bfloat16*>(ahb + base) = h;
        *reinterpret_cast<__nv_bfloat16*>(alb + base) = l;
    }
}

// ---------------------------------------------------------------------------
// Kernel 2: fused convert+GEMM, warp-specialized, 3-stage ring,
// IN-PLACE x conversion (raw fp32 tile -> bf16 hi/lo in the same 14 KB).
// Roles: warps 0-3 convert x (+epilogue), warp 4 = bulk-load producer,
//        warp 5 lane0 = MMA issuer.
// ---------------------------------------------------------------------------
#define TN 112                      // 784 = 7*112
#define NTHREADS 192

#define AT_BYTES (COUT * 64)        // 24576 per A term per chunk
#define XC_BYTES (TN * 64)          // 7168 per converted X term
#define XR_BYTES (KC * TN * 4)      // 14336 raw fp32 x tile (== 2 * XC_BYTES)
#define AH_OFF 0
#define AL_OFF AT_BYTES
#define XR_OFF (2 * AT_BYTES)                   // raw tile lands here...
#define XH_OFF XR_OFF                           // ...hi overwrites first half
#define XL_OFF (XR_OFF + XC_BYTES)              // ...lo overwrites second half
#define STAGE_BYTES (XR_OFF + XR_BYTES)         // 63488
#define TOT_TX STAGE_BYTES
#define NSTAGE 3
#define SM_STAGE0 1024
#define SM_TOTAL (SM_STAGE0 + NSTAGE * STAGE_BYTES)  // 191488

// idesc: F32 accum, BF16 x BF16, K-major both, N=112, M=128
#define IDESC ((1u << 4) | (1u << 7) | (1u << 10) | ((TN / 8) << 17) | ((128 / 16) << 24))

#if HAS_TCGEN05
__device__ __forceinline__ uint32_t smem_u32(const void* p) {
    uint32_t a;
    asm("{ .reg .u64 t; cvta.to.shared.u64 t, %1; cvt.u32.u64 %0, t; }" : "=r"(a) : "l"(p));
    return a;
}

#define MBARRIER_INIT(addr, cnt) \
    asm volatile("mbarrier.init.shared.b64 [%0], %1;" :: "r"(addr), "r"(cnt) : "memory")
#define MBARRIER_EXPECT_TX(addr, tx) \
    asm volatile("mbarrier.arrive.expect_tx.shared.b64 _, [%0], %1;" \
        :: "r"(addr), "r"((uint32_t)(tx)) : "memory")
#define MBARRIER_ARRIVE(addr) \
    asm volatile("mbarrier.arrive.shared.b64 _, [%0];" :: "r"(addr) : "memory")

#define MBARRIER_WAIT_PARITY(addr, par) do {                                   \
    uint32_t _m = (addr), _p = (par), _d;                                      \
    asm volatile("{\n\t.reg .pred p;\n\t"                                      \
        "mbarrier.try_wait.parity.acquire.cta.shared::cta.b64 p, [%1], %2;\n\t"\
        "selp.b32 %0, 1, 0, p;\n\t}" : "=r"(_d) : "r"(_m), "r"(_p) : "memory");\
    if (!_d) {                                                                 \
        asm volatile("{\n\t.reg .pred P1;\n\t"                                 \
            "WL_%=:\n\t"                                                       \
            "mbarrier.try_wait.parity.acquire.cta.shared::cta.b64 P1, [%0], %1, 0x989680;\n\t" \
            "@P1 bra.uni WD_%=;\n\t"                                           \
            "bra.uni WL_%=;\n\t"                                               \
            "WD_%=:\n\t}" :: "r"(_m), "r"(_p) : "memory");                     \
    }                                                                          \
} while (0)

#define BULK_G2S(dst, src, bytes, mbar) \
    asm volatile("cp.async.bulk.shared::cluster.global.mbarrier::complete_tx::bytes " \
        "[%0], [%1], %2, [%3];" \
        :: "r"(dst), "l"(src), "r"((uint32_t)(bytes)), "r"(mbar) : "memory")

#define TCGEN05_ALLOC(sm_res, n) \
    asm volatile("tcgen05.alloc.cta_group::1.sync.aligned.shared::cta.b32 [%0], %1;" \
        :: "r"(sm_res), "r"((uint32_t)(n)) : "memory")
#define TCGEN05_RELINQ() \
    asm volatile("tcgen05.relinquish_alloc_permit.cta_group::1.sync.aligned;")
#define TCGEN05_DEALLOC(t, n) \
    asm volatile("tcgen05.dealloc.cta_group::1.sync.aligned.b32 %0, %1;" :: "r"(t), "r"((uint32_t)(n)))
#define TCGEN05_COMMIT(mbar) \
    asm volatile("tcgen05.commit.cta_group::1.mbarrier::arrive::one.shared::cluster.b64 [%0];" \
        :: "r"(mbar) : "memory")
#define TCGEN05_FENCE_AFTER()  asm volatile("tcgen05.fence::after_thread_sync;" ::: "memory")
#define TCGEN05_FENCE_BEFORE() asm volatile("tcgen05.fence::before_thread_sync;" ::: "memory")
#define TCGEN05_WAIT_LD()      asm volatile("tcgen05.wait::ld.sync.aligned;" ::: "memory")
#define FENCE_ASYNC_SHARED()   asm volatile("fence.proxy.async.shared::cta;" ::: "memory")
#define NAMED_BAR(id, cnt)     asm volatile("bar.sync %0, %1;" :: "r"(id), "r"(cnt) : "memory")

__device__ __forceinline__ void mma_f16_ss(uint32_t d, uint64_t a, uint64_t b,
                                           uint32_t idesc, uint32_t en) {
    asm volatile("{\n\t.reg .pred p;\n\t"
        "setp.ne.u32 p, %5, 0;\n\t"
        "tcgen05.mma.cta_group::1.kind::f16 [%0], %1, %2, %3, {%4, %4, %4, %4}, p;\n\t}"
        :: "r"(d), "l"(a), "l"(b), "r"(idesc), "r"(0u), "r"(en) : "memory");
}

// SW64 K-major descriptor: layout=4, version=1, SBO=32, LBO=1
static constexpr uint64_t DESC_BASE_SW64 =
    (uint64_t(4) << 61) | (uint64_t(1) << 46) | (uint64_t(32) << 32) | (uint64_t(1) << 16);
#define MAKE_DESC(a) (DESC_BASE_SW64 | ((uint64_t)((a) >> 4) & 0x3FFF))

#define LDTM_X32(r, t) \
    asm volatile("tcgen05.ld.sync.aligned.32x32b.x32.b32 " \
        "{%0,%1,%2,%3,%4,%5,%6,%7,%8,%9,%10,%11,%12,%13,%14,%15," \
        "%16,%17,%18,%19,%20,%21,%22,%23,%24,%25,%26,%27,%28,%29,%30,%31}, [%32];" \
        : "=r"((r)[0]),"=r"((r)[1]),"=r"((r)[2]),"=r"((r)[3]),"=r"((r)[4]),"=r"((r)[5]),"=r"((r)[6]),"=r"((r)[7]), \
          "=r"((r)[8]),"=r"((r)[9]),"=r"((r)[10]),"=r"((r)[11]),"=r"((r)[12]),"=r"((r)[13]),"=r"((r)[14]),"=r"((r)[15]), \
          "=r"((r)[16]),"=r"((r)[17]),"=r"((r)[18]),"=r"((r)[19]),"=r"((r)[20]),"=r"((r)[21]),"=r"((r)[22]),"=r"((r)[23]), \
          "=r"((r)[24]),"=r"((r)[25]),"=r"((r)[26]),"=r"((r)[27]),"=r"((r)[28]),"=r"((r)[29]),"=r"((r)[30]),"=r"((r)[31]) \
        : "r"(t))

#define LDTM_X16(r, t) \
    asm volatile("tcgen05.ld.sync.aligned.32x32b.x16.b32 " \
        "{%0,%1,%2,%3,%4,%5,%6,%7,%8,%9,%10,%11,%12,%13,%14,%15}, [%16];" \
        : "=r"((r)[0]),"=r"((r)[1]),"=r"((r)[2]),"=r"((r)[3]),"=r"((r)[4]),"=r"((r)[5]),"=r"((r)[6]),"=r"((r)[7]), \
          "=r"((r)[8]),"=r"((r)[9]),"=r"((r)[10]),"=r"((r)[11]),"=r"((r)[12]),"=r"((r)[13]),"=r"((r)[14]),"=r"((r)[15]) \
        : "r"(t))
#endif  // HAS_TCGEN05

__global__ __launch_bounds__(NTHREADS, 1)
void gemm_kernel(const __nv_bfloat16* __restrict__ ah,
                 const __nv_bfloat16* __restrict__ al,
                 const float* __restrict__ x,
                 const float* __restrict__ rw,
                 const float* __restrict__ w,
                 float* __restrict__ out)
{
    extern __shared__ char smem[];
    const int tid = threadIdx.x;
    const int n0 = blockIdx.x * TN;
    const int b  = blockIdx.y;

#if HAS_TCGEN05
    (void)rw; (void)w;
    const uint32_t smem_base = smem_u32(smem);
    uint32_t full[NSTAGE], cbar[NSTAGE], mmad[NSTAGE];
#pragma unroll
    for (int s = 0; s < NSTAGE; s++) {
        full[s] = smem_base + 8  + 8 * s;
        cbar[s] = smem_base + 32 + 8 * s;
        mmad[s] = smem_base + 56 + 8 * s;
    }
    const uint32_t mb_done = smem_base + 80;

    const int wid = tid >> 5, lid = tid & 31;

    if (wid == 0) TCGEN05_ALLOC(smem_base, 512);
    if (tid == 0) {
#pragma unroll
        for (int s = 0; s < NSTAGE; s++) {
            MBARRIER_INIT(full[s], 1);
            MBARRIER_INIT(cbar[s], 128);   // converter warps 0-3
            MBARRIER_INIT(mmad[s], 1);
        }
        MBARRIER_INIT(mb_done, 1);
    }
    if (wid == 0) TCGEN05_RELINQ();
    __syncthreads();

    uint32_t tmem_base;
    asm volatile("ld.shared.b32 %0, [%1];" : "=r"(tmem_base) : "r"(smem_base));

    // GMEM bases
    const char*  gah = (const char*)ah + (size_t)b * NCHUNK * AT_BYTES;
    const char*  gal = (const char*)al + (size_t)b * NCHUNK * AT_BYTES;
    const float* gx  = x + (size_t)b * CIN * HW + n0;   // rows stride HW

    if (wid == 4) {
        // ---------- producer warp: TMA issue spread across lanes ----------
        for (int c = 0; c < NCHUNK; c++) {
            const int s = c % NSTAGE;
            if (lid == 0) {
                if (c >= NSTAGE)
                    MBARRIER_WAIT_PARITY(mmad[s], ((c - NSTAGE) / NSTAGE) & 1);
                MBARRIER_EXPECT_TX(full[s], TOT_TX);
            }
            __syncwarp();
            const uint32_t stg = smem_base + SM_STAGE0 + s * STAGE_BYTES;
            // each lane issues one x row
            BULK_G2S(stg + XR_OFF + lid * (TN * 4),
                     gx + (size_t)(c * KC + lid) * HW, TN * 4, full[s]);
            if (lid == 0)
                BULK_G2S(stg + AH_OFF, gah + (size_t)c * AT_BYTES, AT_BYTES, full[s]);
            else if (lid == 1)
                BULK_G2S(stg + AL_OFF, gal + (size_t)c * AT_BYTES, AT_BYTES, full[s]);
        }
    } else if (wid == 5) {
        // ------------------- MMA issuer (lane 0) -------------------
        if (lid == 0) {
            for (int c = 0; c < NCHUNK; c++) {
                const int s = c % NSTAGE;
                MBARRIER_WAIT_PARITY(cbar[s], (c / NSTAGE) & 1);
                const uint32_t stg = smem_base + SM_STAGE0 + s * STAGE_BYTES;
                const uint64_t dah = MAKE_DESC(stg + AH_OFF);
                const uint64_t dal = MAKE_DESC(stg + AL_OFF);
                const uint64_t dxh = MAKE_DESC(stg + XH_OFF);
                const uint64_t dxl = MAKE_DESC(stg + XL_OFF);
#pragma unroll
                for (int t = 0; t < 3; t++) {
                    const uint32_t d  = tmem_base + t * TN;
                    const uint64_t at = (uint64_t)t * 512;   // 128 rows * 64B / 16
                    mma_f16_ss(d, dah + at,     dxh,     IDESC, c > 0 ? 1u : 0u);
                    mma_f16_ss(d, dah + at + 2, dxh + 2, IDESC, 1u);
                    mma_f16_ss(d, dal + at,     dxh,     IDESC, 1u);
                    mma_f16_ss(d, dal + at + 2, dxh + 2, IDESC, 1u);
                    mma_f16_ss(d, dah + at,     dxl,     IDESC, 1u);
                    mma_f16_ss(d, dah + at + 2, dxl + 2, IDESC, 1u);
                }
                TCGEN05_COMMIT(c == NCHUNK - 1 ? mb_done : mmad[s]);
            }
        }
    } else {
        // ------------------- converters (warps 0-3) -------------------
        // In-place: read raw fp32 column into regs, barrier, write bf16 hi/lo
        // back over the same 14 KB region (SW64 swizzled K-major rows).
        const int ncv = tid;          // 0..127; rows 0..111 valid
        for (int c = 0; c < NCHUNK; c++) {
            const int s = c % NSTAGE;
            MBARRIER_WAIT_PARITY(full[s], (c / NSTAGE) & 1);
            char* stp = smem + SM_STAGE0 + s * STAGE_BYTES;
            uint32_t hw_[16], lw_[16];
            if (ncv < TN) {
                const float* xr = reinterpret_cast<const float*>(stp + XR_OFF);
                float raw[KC];
#pragma unroll
                for (int kk = 0; kk < KC; kk++) raw[kk] = xr[kk * TN + ncv];
#pragma unroll
                for (int kk = 0; kk < 16; kk++) {
                    float v0 = raw[2 * kk], v1 = raw[2 * kk + 1];
                    __nv_bfloat16 h0 = __float2bfloat16(v0);
                    __nv_bfloat16 h1 = __float2bfloat16(v1);
                    __nv_bfloat16 l0 = __float2bfloat16(v0 - __bfloat162float(h0));
                    __nv_bfloat16 l1 = __float2bfloat16(v1 - __bfloat162float(h1));
                    __nv_bfloat162 hp = {h0, h1}, lp = {l0, l1};
                    hw_[kk] = *reinterpret_cast<uint32_t*>(&hp);
                    lw_[kk] = *reinterpret_cast<uint32_t*>(&lp);
                }
            }
            // all reads of the raw tile complete before any overwrite
            NAMED_BAR(1, 128);
            if (ncv < TN) {
#pragma unroll
                for (int q = 0; q < 4; q++) {
                    uint32_t off = sw64((uint32_t)(ncv * 64 + q * 16));
                    *reinterpret_cast<uint4*>(stp + XH_OFF + off) =
                        make_uint4(hw_[4*q], hw_[4*q+1], hw_[4*q+2], hw_[4*q+3]);
                    *reinterpret_cast<uint4*>(stp + XL_OFF + off) =
                        make_uint4(lw_[4*q], lw_[4*q+1], lw_[4*q+2], lw_[4*q+3]);
                }
            }
            FENCE_ASYNC_SHARED();
            MBARRIER_ARRIVE(cbar[s]);
        }
    }

    // ---- epilogue ----
    MBARRIER_WAIT_PARITY(mb_done, 0);
    TCGEN05_FENCE_AFTER();

    if (wid < 4) {
        uint32_t r[32];
#pragma unroll
        for (int t = 0; t < 3; t++) {
            const int m = t * 128 + wid * 32 + lid;
            float* orow = out + ((size_t)b * COUT + m) * HW + n0;
            const uint32_t tb = tmem_base + t * TN;

            LDTM_X32(r, tb);
            TCGEN05_WAIT_LD();
#pragma unroll
            for (int q = 0; q < 8; q++)
                *reinterpret_cast<float4*>(orow + q * 4) =
                    make_float4(__uint_as_float(r[q*4]), __uint_as_float(r[q*4+1]),
                                __uint_as_float(r[q*4+2]), __uint_as_float(r[q*4+3]));
            LDTM_X32(r, tb + 32);
            TCGEN05_WAIT_LD();
#pragma unroll
            for (int q = 0; q < 8; q++)
                *reinterpret_cast<float4*>(orow + 32 + q * 4) =
                    make_float4(__uint_as_float(r[q*4]), __uint_as_float(r[q*4+1]),
                                __uint_as_float(r[q*4+2]), __uint_as_float(r[q*4+3]));
            LDTM_X32(r, tb + 64);
            TCGEN05_WAIT_LD();
#pragma unroll
            for (int q = 0; q < 8; q++)
                *reinterpret_cast<float4*>(orow + 64 + q * 4) =
                    make_float4(__uint_as_float(r[q*4]), __uint_as_float(r[q*4+1]),
                                __uint_as_float(r[q*4+2]), __uint_as_float(r[q*4+3]));
            LDTM_X16(r, tb + 96);
            TCGEN05_WAIT_LD();
#pragma unroll
            for (int q = 0; q < 4; q++)
                *reinterpret_cast<float4*>(orow + 96 + q * 4) =
                    make_float4(__uint_as_float(r[q*4]), __uint_as_float(r[q*4+1]),
                                __uint_as_float(r[q*4+2]), __uint_as_float(r[q*4+3]));
        }
        TCGEN05_FENCE_BEFORE();
    }

    __syncthreads();
    if (wid == 0) TCGEN05_DEALLOC(tmem_base, 512);

#else  // ---------- SIMT fallback (compute_103 pass only; never executes) ----
    (void)ah; (void)al; (void)smem;
    for (int idx = tid; idx < COUT * TN; idx += NTHREADS) {
        const int o = idx / TN;
        const int n = n0 + idx % TN;
        float acc = 0.f;
        for (int k = 0; k < CIN; k++) {
            float a = 0.f;
#pragma unroll
            for (int e = 0; e < NEXP; e++)
                a = fmaf(rw[b * NEXP + e], w[(size_t)e * COUT * CIN + o * CIN + k], a);
            acc = fmaf(a, x[(size_t)b * CIN * HW + (size_t)k * HW + n], acc);
        }
        out[((size_t)b * COUT + o) * HW + n] = acc;
    }
#endif
}

// ---------------------------------------------------------------------------
extern "C" void kernel_launch(void* const* d_in, const int* in_sizes, int n_in,
                              void* d_out, int out_size)
{
    const float* x  = (const float*)d_in[0];
    const float* rw = (const float*)d_in[1];
    const float* w  = (const float*)d_in[2];
    float* out = (float*)d_out;

    __nv_bfloat16 *ah, *al;
    cudaGetSymbolAddress((void**)&ah, g_a_hi);
    cudaGetSymbolAddress((void**)&al, g_a_lo);

    {
        const int total = COUT * CIN;
        agg_kernel<<<(total + 255) / 256, 256>>>(rw, w, ah, al);
    }
    {
        cudaFuncSetAttribute(gemm_kernel, cudaFuncAttributeMaxDynamicSharedMemorySize, SM_TOTAL);
        dim3 grid(HW / TN, BATCH);   // 7 x 64 = 448 CTAs
        gemm_kernel<<<grid, NTHREADS, SM_TOTAL>>>(ah, al, x, rw, w, out);
    }
}